// round 15
// baseline (speedup 1.0000x reference)
#include <cuda_runtime.h>
#include <cuda_fp16.h>
#include <cstdint>

// Problem constants
#define Bc   1024
#define Tc   512
#define EMBc 100
#define KP   112   // padded K for layer-1 gemm (fp16, zero-filled)
#define H1c  128
#define G1c  512   // 4*H1
#define H2c  64
#define G2c  256   // 4*H2
#define Mtot (Bc*Tc)  // 524288

// Scratch (fp16)
__device__ __half g_xh [(size_t)Mtot * KP];   // padded fp16 X
__device__ __half g_w1h[(size_t)G1c * KP];    // padded fp16 W1_ih
__device__ __half g_xw1[(size_t)Mtot * G1c];  // layer-1 gate preactivations [b][t][512]

// ---------------------------------------------------------------------------
// helpers
// ---------------------------------------------------------------------------
__device__ __forceinline__ uint32_t s2u(const void* p) {
    return (uint32_t)__cvta_generic_to_shared(p);
}
__device__ __forceinline__ void ldm_x4(uint32_t& a0, uint32_t& a1, uint32_t& a2, uint32_t& a3,
                                       uint32_t addr) {
    asm volatile("ldmatrix.sync.aligned.m8n8.x4.shared.b16 {%0,%1,%2,%3}, [%4];"
                 : "=r"(a0), "=r"(a1), "=r"(a2), "=r"(a3) : "r"(addr));
}
__device__ __forceinline__ void ldm_x2(uint32_t& b0, uint32_t& b1, uint32_t addr) {
    asm volatile("ldmatrix.sync.aligned.m8n8.x2.shared.b16 {%0,%1}, [%2];"
                 : "=r"(b0), "=r"(b1) : "r"(addr));
}
__device__ __forceinline__ void mma16816(float* d, const uint32_t* a, const uint32_t* b) {
    asm volatile("mma.sync.aligned.m16n8k16.row.col.f32.f16.f16.f32 "
                 "{%0,%1,%2,%3}, {%4,%5,%6,%7}, {%8,%9}, {%0,%1,%2,%3};"
                 : "+f"(d[0]), "+f"(d[1]), "+f"(d[2]), "+f"(d[3])
                 : "r"(a[0]), "r"(a[1]), "r"(a[2]), "r"(a[3]), "r"(b[0]), "r"(b[1]));
}
__device__ __forceinline__ float tanhfast(float x) {
    float y;
    asm("tanh.approx.f32 %0, %1;" : "=f"(y) : "f"(x));
    return y;
}
__device__ __forceinline__ float sigfast(float x) {
    return 0.5f * tanhfast(0.5f * x) + 0.5f;
}
__device__ __forceinline__ uint32_t packh2(float x, float y) {
    __half2 h = __floats2half2_rn(x, y);
    return *reinterpret_cast<uint32_t*>(&h);
}
__device__ __forceinline__ void cp16(uint32_t smem_addr, const void* gptr) {
    asm volatile("cp.async.cg.shared.global [%0], [%1], 16;" :: "r"(smem_addr), "l"(gptr));
}
__device__ __forceinline__ void cp_commit() { asm volatile("cp.async.commit_group;"); }
__device__ __forceinline__ void cp_wait0()  { asm volatile("cp.async.wait_group 0;"); }

// ---------------------------------------------------------------------------
// fp32 [rows][EMBc] -> fp16 [rows][KP], zero-padded.
// ---------------------------------------------------------------------------
__global__ void convert_pad(const float* __restrict__ src, __half* __restrict__ dst, int rows)
{
    int gid = blockIdx.x * blockDim.x + threadIdx.x;
    int total = rows * (KP / 2);
    if (gid >= total) return;
    int row = gid / (KP / 2);
    int p   = gid - row * (KP / 2);
    int k   = 2 * p;
    float x0 = (k < EMBc)     ? src[(size_t)row * EMBc + k]     : 0.f;
    float x1 = (k + 1 < EMBc) ? src[(size_t)row * EMBc + k + 1] : 0.f;
    *(__half2*)(dst + (size_t)row * KP + k) = __floats2half2_rn(x0, x1);
}

// ---------------------------------------------------------------------------
// Layer-1 GEMM (known-good): fp16 in / fp16 out, K=112 single smem tile.
// ---------------------------------------------------------------------------
__global__ void __launch_bounds__(256) gemm1h(const __half* __restrict__ A,   // [M][112]
                                              const __half* __restrict__ W,   // [512][112]
                                              const float* __restrict__ ba,
                                              const float* __restrict__ bb,
                                              __half* __restrict__ out)
{
    constexpr int LDSs = 120;
    __shared__ alignas(16) __half As[128 * LDSs];
    __shared__ alignas(16) __half Ws[128 * LDSs];

    const int tid  = threadIdx.x;
    const int bm   = blockIdx.y * 128;
    const int bn   = blockIdx.x * 128;
    const int w    = tid >> 5;
    const int lane = tid & 31;
    const int wm   = (w >> 2) * 64;
    const int wn   = (w & 3) * 32;

    {
        const int m = tid >> 1;
#pragma unroll
        for (int c = 0; c < 7; c++) {
            int cc = c * 2 + (tid & 1);
            cp16(s2u(&As[m * LDSs + cc * 8]), A + (size_t)(bm + m) * KP + cc * 8);
            cp16(s2u(&Ws[m * LDSs + cc * 8]), W + (size_t)(bn + m) * KP + cc * 8);
        }
        cp_commit();
        cp_wait0();
    }
    __syncthreads();

    float acc[4][4][4];
#pragma unroll
    for (int mt = 0; mt < 4; mt++)
#pragma unroll
        for (int nt = 0; nt < 4; nt++)
#pragma unroll
            for (int i = 0; i < 4; i++) acc[mt][nt][i] = 0.f;

#pragma unroll
    for (int ks = 0; ks < 7; ks++) {
        uint32_t af[4][4];
#pragma unroll
        for (int mt = 0; mt < 4; mt++) {
            uint32_t addr = s2u(&As[(wm + mt * 16 + (lane & 15)) * LDSs + ks * 16 + (lane >> 4) * 8]);
            ldm_x4(af[mt][0], af[mt][1], af[mt][2], af[mt][3], addr);
        }
        uint32_t bf[4][2];
#pragma unroll
        for (int nt = 0; nt < 4; nt++) {
            int l = lane & 15;
            uint32_t addr = s2u(&Ws[(wn + nt * 8 + (l & 7)) * LDSs + ks * 16 + ((l >> 3) & 1) * 8]);
            ldm_x2(bf[nt][0], bf[nt][1], addr);
        }
#pragma unroll
        for (int mt = 0; mt < 4; mt++)
#pragma unroll
            for (int nt = 0; nt < 4; nt++)
                mma16816(acc[mt][nt], af[mt], bf[nt]);
    }

#pragma unroll
    for (int mt = 0; mt < 4; mt++) {
#pragma unroll
        for (int nt = 0; nt < 4; nt++) {
            int row = bm + wm + mt * 16 + (lane >> 2);
            int col = bn + wn + nt * 8 + (lane & 3) * 2;
            float b0 = __ldg(ba + col) + __ldg(bb + col);
            float b1 = __ldg(ba + col + 1) + __ldg(bb + col + 1);
            *(__half2*)(out + (size_t)row * G1c + col) =
                __floats2half2_rn(acc[mt][nt][0] + b0, acc[mt][nt][1] + b1);
            *(__half2*)(out + (size_t)(row + 8) * G1c + col) =
                __floats2half2_rn(acc[mt][nt][2] + b0, acc[mt][nt][3] + b1);
        }
    }
}

// ---------------------------------------------------------------------------
// FUSED layer-1 + layer-2 recurrence + FC head (R12 base).
// R15 deltas:
//  - h1 triple-buffered; L2 delayed by 2 (computes h2[t-2] at iter t)
//  - W2ih A-fragments loaded once per TWO steps (even iters), second step's
//    partial gates carried in registers (pP)
//  - all B-fragments via ldm_x4 (half the LDSM instructions)
// ---------------------------------------------------------------------------
#define HP1f 136
#define HP2f 72
#define XPf  520
#define WISf 136
#define WHSf 72
#define SM_WIH   (256 * WISf * 2)                  // 69632
#define SM_WHH   (256 * WHSf * 2)                  // 36864
#define SM_XWB   (2 * 8 * XPf * 2)                 // 16640
#define SM_HSH1  (3 * 8 * HP1f * 2)                // 6528
#define SM_HSH2  (2 * 8 * HP2f * 2)                // 2304
#define SM_HFIN  (8 * 64 * 4)                      // 2048
#define SMEMF (SM_WIH + SM_WHH + SM_XWB + SM_HSH1 + SM_HSH2 + SM_HFIN)

__global__ void __launch_bounds__(512) lstm12_kernel(
    const __half* __restrict__ xw,    // [B][T][512]
    const float* __restrict__ W1hh,   // [512][128]
    const float* __restrict__ W2ih,   // [256][128]
    const float* __restrict__ W2hh,   // [256][64]
    const float* __restrict__ b2_ih,
    const float* __restrict__ b2_hh,
    const float* __restrict__ fc1w,
    const float* __restrict__ fc1b,
    const float* __restrict__ fc2w,
    const float* __restrict__ fc2b,
    float* __restrict__ out)
{
    extern __shared__ char smraw[];
    __half* Wihs = (__half*)smraw;
    __half* Whhs = (__half*)(smraw + SM_WIH);
    __half* xwb  = (__half*)(smraw + SM_WIH + SM_WHH);
    __half* hsh1 = (__half*)(smraw + SM_WIH + SM_WHH + SM_XWB);
    __half* hsh2 = (__half*)(smraw + SM_WIH + SM_WHH + SM_XWB + SM_HSH1);
    float*  hfin = (float*)(smraw + SM_WIH + SM_WHH + SM_XWB + SM_HSH1 + SM_HSH2);

    const int tid  = threadIdx.x;
    const int w    = tid >> 5;
    const int lane = tid & 31;
    const int b0   = blockIdx.x * 8;
    const int r    = lane >> 2;
    const int q    = lane & 3;
    const int n0   = q * 2;
    const bool lo  = (r < 4);
    const int ncol = n0 + (lo ? 0 : 1);

    // ---- L1 mapping (16 warps x 2 m16 tiles, gate-permuted) ----
    int uu[2], Glo1[2], Ghi1[2];
#pragma unroll
    for (int mt = 0; mt < 2; mt++) {
        uu[mt]   = w * 8 + mt * 4 + (r & 3);
        Glo1[mt] = (r >> 2) * H1c + uu[mt];
        Ghi1[mt] = ((r + 8) >> 2) * H1c + uu[mt];
    }
    // persistent W1_hh fragments (64 regs)
    uint32_t afr[2][8][4];
#pragma unroll
    for (int mt = 0; mt < 2; mt++) {
        const float* rl = W1hh + (size_t)Glo1[mt] * H1c;
        const float* rh = W1hh + (size_t)Ghi1[mt] * H1c;
#pragma unroll
        for (int ks = 0; ks < 8; ks++) {
            int k = ks * 16 + q * 2;
            afr[mt][ks][0] = packh2(rl[k],     rl[k + 1]);
            afr[mt][ks][1] = packh2(rh[k],     rh[k + 1]);
            afr[mt][ks][2] = packh2(rl[k + 8], rl[k + 9]);
            afr[mt][ks][3] = packh2(rh[k + 8], rh[k + 9]);
        }
    }

    // ---- L2 mapping (16 warps x 1 m16 tile) ----
    const int u    = w * 4 + (r & 3);
    const int Glo2 = (r >> 2) * H2c + u;
    const int Ghi2 = ((r + 8) >> 2) * H2c + u;
    const float blo = __ldg(b2_ih + Glo2) + __ldg(b2_hh + Glo2);
    const float bhi = __ldg(b2_ih + Ghi2) + __ldg(b2_hh + Ghi2);

    // ---- stage W2 into smem, PERMUTED rows: tr -> src gate-unit row ----
    for (int idx = tid; idx < 256 * 128; idx += 512) {
        int tr = idx >> 7, k = idx & 127;
        int pr = tr & 15, ww = tr >> 4;
        int src = (pr >> 2) * 64 + ww * 4 + (pr & 3);
        Wihs[tr * WISf + k] = __float2half_rn(W2ih[(size_t)src * 128 + k]);
    }
    for (int idx = tid; idx < 256 * 64; idx += 512) {
        int tr = idx >> 6, k = idx & 63;
        int pr = tr & 15, ww = tr >> 4;
        int src = (pr >> 2) * 64 + ww * 4 + (pr & 3);
        Whhs[tr * WHSf + k] = __float2half_rn(W2hh[(size_t)src * 64 + k]);
    }

    // zero h states (all buffers)
    for (int i = tid; i < 3 * 8 * HP1f / 2; i += 512)
        ((__half2*)hsh1)[i] = __floats2half2_rn(0.f, 0.f);
    for (int i = tid; i < 2 * 8 * HP2f / 2; i += 512)
        ((__half2*)hsh2)[i] = __floats2half2_rn(0.f, 0.f);

    // prefetch xw tile for t=0
    {
        int row = tid >> 6, ch = tid & 63;
        cp16(s2u(&xwb[0 * 8 * XPf + row * XPf + ch * 8]),
             xw + ((size_t)(b0 + row) * Tc + 0) * G1c + ch * 8);
        cp_commit();
        cp_wait0();
    }
    __syncthreads();

    // precomputed smem byte-addresses for L2 A-frag ldm_x4
    const uint32_t aih_base = s2u(Wihs + (w * 16 + (lane & 15)) * WISf + (lane >> 4) * 8);
    const uint32_t ahh_base = s2u(Whhs + (w * 16 + (lane & 15)) * WHSf + (lane >> 4) * 8);
    // per-lane B-frag base offsets (bytes) for ldm_x4 over k-pairs
    const uint32_t bB1off = (uint32_t)((lane & 7) * (HP1f * 2) + (lane >> 3) * 16);
    const uint32_t bB2off = (uint32_t)((lane & 7) * (HP2f * 2) + (lane >> 3) * 16);

    float cst1[2] = {0.f, 0.f};
    float cst2 = 0.f;
    float pP[4] = {0.f, 0.f, 0.f, 0.f};   // carried W2ih partial gates (odd steps)

    for (int t = 0; t <= Tc + 1; t++) {
        if (t + 1 < Tc) {
            int row = tid >> 6, ch = tid & 63;
            cp16(s2u(&xwb[((t + 1) & 1) * 8 * XPf + row * XPf + ch * 8]),
                 xw + ((size_t)(b0 + row) * Tc + (t + 1)) * G1c + ch * 8);
            cp_commit();
        }

        const __half* xb   = xwb  + (t & 1) * 8 * XPf;
        const __half* h1r1 = hsh1 + ((t + 2) % 3) * 8 * HP1f;   // h1[t-1]
        const __half* h1r2 = hsh1 + ((t + 1) % 3) * 8 * HP1f;   // h1[t-2]
        __half*       h1w  = hsh1 + (t % 3) * 8 * HP1f;         // h1[t]
        const __half* h2r  = hsh2 + ((t + 1) & 1) * 8 * HP2f;   // h2[t-3]
        __half*       h2w  = hsh2 + (t & 1) * 8 * HP2f;         // h2[t-2]

        // ---- L1: h1[t] = LSTM1(xw_t, h1[t-1]) ----
        if (t < Tc) {
            float acc1[2][4];
            acc1[0][0] = __half2float(xb[n0 * XPf + Glo1[0]]);
            acc1[0][1] = __half2float(xb[(n0 + 1) * XPf + Glo1[0]]);
            acc1[0][2] = __half2float(xb[n0 * XPf + Ghi1[0]]);
            acc1[0][3] = __half2float(xb[(n0 + 1) * XPf + Ghi1[0]]);
            acc1[1][0] = __half2float(xb[n0 * XPf + Glo1[1]]);
            acc1[1][1] = __half2float(xb[(n0 + 1) * XPf + Glo1[1]]);
            acc1[1][2] = __half2float(xb[n0 * XPf + Ghi1[1]]);
            acc1[1][3] = __half2float(xb[(n0 + 1) * XPf + Ghi1[1]]);

            const uint32_t b1base = s2u(h1r1) + bB1off;
#pragma unroll
            for (int kp = 0; kp < 4; kp++) {
                uint32_t bq[4];
                ldm_x4(bq[0], bq[1], bq[2], bq[3], b1base + kp * 64);
                mma16816(acc1[0], afr[0][2 * kp],     &bq[0]);
                mma16816(acc1[1], afr[1][2 * kp],     &bq[0]);
                mma16816(acc1[0], afr[0][2 * kp + 1], &bq[2]);
                mma16816(acc1[1], afr[1][2 * kp + 1], &bq[2]);
            }
#pragma unroll
            for (int mt = 0; mt < 2; mt++) {
                float s0 = lo ? acc1[mt][1] : acc1[mt][0];
                float s1 = lo ? acc1[mt][3] : acc1[mt][2];
                float r0 = __shfl_xor_sync(0xffffffffu, s0, 16);
                float r1 = __shfl_xor_sync(0xffffffffu, s1, 16);
                float zi = lo ? acc1[mt][0] : r0;
                float zf = lo ? r0          : acc1[mt][1];
                float zg = lo ? acc1[mt][2] : r1;
                float zo = lo ? r1          : acc1[mt][3];

                cst1[mt] = sigfast(zf) * cst1[mt] + sigfast(zi) * tanhfast(zg);
                float h = sigfast(zo) * tanhfast(cst1[mt]);
                h1w[ncol * HP1f + uu[mt]] = __float2half_rn(h);
            }
        }

        // ---- L2: h2[t-2] = LSTM2(h1[t-2], h2[t-3]) ----
        if (t >= 2) {
            // recurrent part: W2hh @ h2[t-3]
            float accC[4] = {0.f, 0.f, 0.f, 0.f};
            {
                const uint32_t b2base = s2u(h2r) + bB2off;
#pragma unroll
                for (int kp = 0; kp < 2; kp++) {
                    uint32_t a0[4], a1[4], bq[4];
                    ldm_x4(a0[0], a0[1], a0[2], a0[3], ahh_base + (2 * kp) * 32);
                    ldm_x4(a1[0], a1[1], a1[2], a1[3], ahh_base + (2 * kp + 1) * 32);
                    ldm_x4(bq[0], bq[1], bq[2], bq[3], b2base + kp * 64);
                    mma16816(accC, a0, &bq[0]);
                    mma16816(accC, a1, &bq[2]);
                }
            }

            float acc[4];
            if ((t & 1) == 0) {
                // input-projection pair: W2ih @ [h1[t-2] | h1[t-1]], A loaded once
                float p0[4] = {blo, blo, bhi, bhi};
                float p1[4] = {blo, blo, bhi, bhi};
                const uint32_t bAbase = s2u(h1r2) + bB1off;
                const uint32_t bBbase = s2u(h1r1) + bB1off;
#pragma unroll
                for (int kp = 0; kp < 4; kp++) {
                    uint32_t a0[4], a1[4], bA[4], bB[4];
                    ldm_x4(a0[0], a0[1], a0[2], a0[3], aih_base + (2 * kp) * 32);
                    ldm_x4(a1[0], a1[1], a1[2], a1[3], aih_base + (2 * kp + 1) * 32);
                    ldm_x4(bA[0], bA[1], bA[2], bA[3], bAbase + kp * 64);
                    ldm_x4(bB[0], bB[1], bB[2], bB[3], bBbase + kp * 64);
                    mma16816(p0, a0, &bA[0]);
                    mma16816(p0, a1, &bA[2]);
                    mma16816(p1, a0, &bB[0]);
                    mma16816(p1, a1, &bB[2]);
                }
#pragma unroll
                for (int i = 0; i < 4; i++) { acc[i] = p0[i] + accC[i]; pP[i] = p1[i]; }
            } else {
#pragma unroll
                for (int i = 0; i < 4; i++) acc[i] = pP[i] + accC[i];
            }

            float s0 = lo ? acc[1] : acc[0];
            float s1 = lo ? acc[3] : acc[2];
            float r0 = __shfl_xor_sync(0xffffffffu, s0, 16);
            float r1 = __shfl_xor_sync(0xffffffffu, s1, 16);
            float zi = lo ? acc[0] : r0;
            float zf = lo ? r0     : acc[1];
            float zg = lo ? acc[2] : r1;
            float zo = lo ? r1     : acc[3];

            cst2 = sigfast(zf) * cst2 + sigfast(zi) * tanhfast(zg);
            float h = sigfast(zo) * tanhfast(cst2);

            if (t == Tc + 1) hfin[ncol * 64 + u] = h;
            else h2w[ncol * HP2f + u] = __float2half_rn(h);
        }

        cp_wait0();
        __syncthreads();
    }

    // FC head: warp w -> batch row w (warps 0..7), lane = fc1 unit
    if (w < 8) {
        float a = __ldg(fc1b + lane);
#pragma unroll
        for (int k = 0; k < 64; k++)
            a = fmaf(hfin[w * 64 + k], __ldg(fc1w + lane * 64 + k), a);
        a = fmaxf(a, 0.f);
        float v = a * __ldg(fc2w + lane);
#pragma unroll
        for (int off = 16; off; off >>= 1) v += __shfl_down_sync(0xffffffffu, v, off);
        if (lane == 0) out[b0 + w] = 1.f / (1.f + __expf(-(v + __ldg(fc2b))));
    }
}

// ---------------------------------------------------------------------------
extern "C" void kernel_launch(void* const* d_in, const int* in_sizes, int n_in,
                              void* d_out, int out_size)
{
    (void)in_sizes; (void)n_in; (void)out_size;
    const float* X     = (const float*)d_in[0];
    const float* W1_ih = (const float*)d_in[1];
    const float* W1_hh = (const float*)d_in[2];
    const float* b1_ih = (const float*)d_in[3];
    const float* b1_hh = (const float*)d_in[4];
    const float* W2_ih = (const float*)d_in[5];
    const float* W2_hh = (const float*)d_in[6];
    const float* b2_ih = (const float*)d_in[7];
    const float* b2_hh = (const float*)d_in[8];
    const float* fc1w  = (const float*)d_in[9];
    const float* fc1b  = (const float*)d_in[10];
    const float* fc2w  = (const float*)d_in[11];
    const float* fc2b  = (const float*)d_in[12];
    float* out = (float*)d_out;

    __half *xh, *w1h, *xw1;
    cudaGetSymbolAddress((void**)&xh,  g_xh);
    cudaGetSymbolAddress((void**)&w1h, g_w1h);
    cudaGetSymbolAddress((void**)&xw1, g_xw1);

    static int attr_done = 0;
    if (!attr_done) {
        cudaFuncSetAttribute(lstm12_kernel, cudaFuncAttributeMaxDynamicSharedMemorySize, SMEMF);
        attr_done = 1;
    }

    // 0) pad+convert X and W1_ih to fp16 [..][112]
    convert_pad<<<(Mtot * (KP / 2) + 255) / 256, 256>>>(X, xh, Mtot);
    convert_pad<<<(G1c * (KP / 2) + 255) / 256, 256>>>(W1_ih, w1h, G1c);
    // 1) xw1 = half(X @ W1_ih^T + b)
    gemm1h<<<dim3(G1c / 128, Mtot / 128), 256>>>(xh, w1h, b1_ih, b1_hh, xw1);
    // 2) fused layer-1 + layer-2 recurrence + FC head
    lstm12_kernel<<<Bc / 8, 512, SMEMF>>>(xw1, W1_hh, W2_ih, W2_hh, b2_ih, b2_hh,
                                          fc1w, fc1b, fc2w, fc2b, out);
}

// round 16
// speedup vs baseline: 1.0433x; 1.0433x over previous
#include <cuda_runtime.h>
#include <cuda_fp16.h>
#include <cstdint>

// Problem constants
#define Bc   1024
#define Tc   512
#define EMBc 100
#define KP   112   // padded K for layer-1 gemm (fp16, zero-filled)
#define H1c  128
#define G1c  512   // 4*H1
#define H2c  64
#define G2c  256   // 4*H2
#define Mtot (Bc*Tc)  // 524288

// Scratch (fp16)
__device__ __half g_xh [(size_t)Mtot * KP];   // padded fp16 X
__device__ __half g_w1h[(size_t)G1c * KP];    // padded fp16 W1_ih
__device__ __half g_xw1[(size_t)Mtot * G1c];  // PERMUTED: [bblk][t][gate512][8]

// ---------------------------------------------------------------------------
// helpers
// ---------------------------------------------------------------------------
__device__ __forceinline__ uint32_t s2u(const void* p) {
    return (uint32_t)__cvta_generic_to_shared(p);
}
__device__ __forceinline__ void ldm_x4(uint32_t& a0, uint32_t& a1, uint32_t& a2, uint32_t& a3,
                                       uint32_t addr) {
    asm volatile("ldmatrix.sync.aligned.m8n8.x4.shared.b16 {%0,%1,%2,%3}, [%4];"
                 : "=r"(a0), "=r"(a1), "=r"(a2), "=r"(a3) : "r"(addr));
}
__device__ __forceinline__ void ldm_x2(uint32_t& b0, uint32_t& b1, uint32_t addr) {
    asm volatile("ldmatrix.sync.aligned.m8n8.x2.shared.b16 {%0,%1}, [%2];"
                 : "=r"(b0), "=r"(b1) : "r"(addr));
}
__device__ __forceinline__ void mma16816(float* d, const uint32_t* a, const uint32_t* b) {
    asm volatile("mma.sync.aligned.m16n8k16.row.col.f32.f16.f16.f32 "
                 "{%0,%1,%2,%3}, {%4,%5,%6,%7}, {%8,%9}, {%0,%1,%2,%3};"
                 : "+f"(d[0]), "+f"(d[1]), "+f"(d[2]), "+f"(d[3])
                 : "r"(a[0]), "r"(a[1]), "r"(a[2]), "r"(a[3]), "r"(b[0]), "r"(b[1]));
}
__device__ __forceinline__ float tanhfast(float x) {
    float y;
    asm("tanh.approx.f32 %0, %1;" : "=f"(y) : "f"(x));
    return y;
}
__device__ __forceinline__ float sigfast(float x) {
    return 0.5f * tanhfast(0.5f * x) + 0.5f;
}
__device__ __forceinline__ uint32_t packh2(float x, float y) {
    __half2 h = __floats2half2_rn(x, y);
    return *reinterpret_cast<uint32_t*>(&h);
}
__device__ __forceinline__ void cp16(uint32_t smem_addr, const void* gptr) {
    asm volatile("cp.async.cg.shared.global [%0], [%1], 16;" :: "r"(smem_addr), "l"(gptr));
}
__device__ __forceinline__ void cp_commit() { asm volatile("cp.async.commit_group;"); }
__device__ __forceinline__ void cp_wait0()  { asm volatile("cp.async.wait_group 0;"); }

// ---------------------------------------------------------------------------
// fp32 [rows][EMBc] -> fp16 [rows][KP], zero-padded.
// ---------------------------------------------------------------------------
__global__ void convert_pad(const float* __restrict__ src, __half* __restrict__ dst, int rows)
{
    int gid = blockIdx.x * blockDim.x + threadIdx.x;
    int total = rows * (KP / 2);
    if (gid >= total) return;
    int row = gid / (KP / 2);
    int p   = gid - row * (KP / 2);
    int k   = 2 * p;
    float x0 = (k < EMBc)     ? src[(size_t)row * EMBc + k]     : 0.f;
    float x1 = (k + 1 < EMBc) ? src[(size_t)row * EMBc + k + 1] : 0.f;
    *(__half2*)(dst + (size_t)row * KP + k) = __floats2half2_rn(x0, x1);
}

// ---------------------------------------------------------------------------
// Layer-1 GEMM with PERMUTED output (tiled so the permutation is coalesced).
// M-tile = 8 batches x 16 timesteps (row r' = ti*8 + bi). After compute,
// the 128x128 result is staged in smem [col][r'] then written as
// [bblk][t][gate][8batch] with fully coalesced STG.128.
// blockIdx.y: bblk = y>>5, t0 = (y&31)*16. blockIdx.x: gate slice (bn).
// ---------------------------------------------------------------------------
__global__ void __launch_bounds__(256) gemm1hp(const __half* __restrict__ A,   // [M][112]
                                               const __half* __restrict__ W,   // [512][112]
                                               const float* __restrict__ ba,
                                               const float* __restrict__ bb,
                                               __half* __restrict__ outp)
{
    constexpr int LDSs = 120;
    constexpr int TS = 136;                      // transpose stage stride (halves)
    __shared__ alignas(16) __half As[128 * LDSs];
    __shared__ alignas(16) __half Ws[128 * LDSs];
    __shared__ alignas(16) __half Tst[128 * TS]; // 34816B stage (fits with As/Ws in 227KB? 
                                                 // As+Ws=61440B, +34816 = 96KB OK as dynamic? static ok)

    const int tid  = threadIdx.x;
    const int bblk = blockIdx.y >> 5;
    const int t0   = (blockIdx.y & 31) * 16;
    const int bn   = blockIdx.x * 128;
    const int w    = tid >> 5;
    const int lane = tid & 31;
    const int wm   = (w >> 2) * 64;
    const int wn   = (w & 3) * 32;

    // load: tile row r' -> global A row m = (bblk*8 + (r'&7))*512 + t0 + (r'>>3)
    {
        const int rp = tid >> 1;
        const size_t arow = ((size_t)(bblk * 8 + (rp & 7)) * Tc + (t0 + (rp >> 3))) * KP;
#pragma unroll
        for (int c = 0; c < 7; c++) {
            int cc = c * 2 + (tid & 1);
            cp16(s2u(&As[rp * LDSs + cc * 8]), A + arow + cc * 8);
            cp16(s2u(&Ws[rp * LDSs + cc * 8]), W + (size_t)(bn + rp) * KP + cc * 8);
        }
        cp_commit();
        cp_wait0();
    }
    __syncthreads();

    float acc[4][4][4];
#pragma unroll
    for (int mt = 0; mt < 4; mt++)
#pragma unroll
        for (int nt = 0; nt < 4; nt++)
#pragma unroll
            for (int i = 0; i < 4; i++) acc[mt][nt][i] = 0.f;

#pragma unroll
    for (int ks = 0; ks < 7; ks++) {
        uint32_t af[4][4];
#pragma unroll
        for (int mt = 0; mt < 4; mt++) {
            uint32_t addr = s2u(&As[(wm + mt * 16 + (lane & 15)) * LDSs + ks * 16 + (lane >> 4) * 8]);
            ldm_x4(af[mt][0], af[mt][1], af[mt][2], af[mt][3], addr);
        }
        uint32_t bf[4][2];
#pragma unroll
        for (int nt = 0; nt < 4; nt++) {
            int l = lane & 15;
            uint32_t addr = s2u(&Ws[(wn + nt * 8 + (l & 7)) * LDSs + ks * 16 + ((l >> 3) & 1) * 8]);
            ldm_x2(bf[nt][0], bf[nt][1], addr);
        }
#pragma unroll
        for (int mt = 0; mt < 4; mt++)
#pragma unroll
            for (int nt = 0; nt < 4; nt++)
                mma16816(acc[mt][nt], af[mt], bf[nt]);
    }
    __syncthreads();   // As/Ws dead; Tst reuse safe

    // stage: Tst[col][r'] (2B scattered STS — cheap, off critical path)
#pragma unroll
    for (int mt = 0; mt < 4; mt++) {
        int rp = wm + mt * 16 + (lane >> 2);
#pragma unroll
        for (int nt = 0; nt < 4; nt++) {
            int col = wn + nt * 8 + (lane & 3) * 2;
            float b0 = __ldg(ba + bn + col) + __ldg(bb + bn + col);
            float b1 = __ldg(ba + bn + col + 1) + __ldg(bb + bn + col + 1);
            Tst[(col)     * TS + rp]     = __float2half_rn(acc[mt][nt][0] + b0);
            Tst[(col + 1) * TS + rp]     = __float2half_rn(acc[mt][nt][1] + b1);
            Tst[(col)     * TS + rp + 8] = __float2half_rn(acc[mt][nt][2] + b0);
            Tst[(col + 1) * TS + rp + 8] = __float2half_rn(acc[mt][nt][3] + b1);
        }
    }
    __syncthreads();

    // coalesced write: chunk c (8 halves) = (ti = c>>7, col = c&127)
    // out half index = ((bblk*512) + t0 + ti)*4096 + (bn+col)*8
    {
        const size_t tilebase = ((size_t)bblk * Tc + t0) * (G1c * 8);
#pragma unroll
        for (int i = 0; i < 8; i++) {
            int c = tid + i * 256;              // 0..2047
            int ti = c >> 7, col = c & 127;
            uint4 v = *(const uint4*)&Tst[col * TS + ti * 8];
            *(uint4*)(outp + tilebase + (size_t)ti * (G1c * 8) + (bn + col) * 8) = v;
        }
    }
}

// ---------------------------------------------------------------------------
// FUSED layer-1 + layer-2 recurrence + FC head — EXACT R12 structure.
// R16 deltas only: xw tile is one contiguous 8KB cp.async (permuted layout),
// acc-init is 4 half2 LDS (2-way conflicts) instead of 8 scalars.
// ---------------------------------------------------------------------------
#define HP1f 136
#define HP2f 72
#define XWT  4096                                  // permuted xw tile (halves)
#define WISf 136
#define WHSf 72
#define SM_WIH   (256 * WISf * 2)                  // 69632
#define SM_WHH   (256 * WHSf * 2)                  // 36864
#define SM_XWB   (2 * XWT * 2)                     // 16384
#define SM_HSH1  (2 * 8 * HP1f * 2)                // 4352
#define SM_HSH2  (2 * 8 * HP2f * 2)                // 2304
#define SM_HFIN  (8 * 64 * 4)                      // 2048
#define SMEMF (SM_WIH + SM_WHH + SM_XWB + SM_HSH1 + SM_HSH2 + SM_HFIN)

__global__ void __launch_bounds__(512) lstm12_kernel(
    const __half* __restrict__ xwp,   // [bblk][t][512][8]
    const float* __restrict__ W1hh,   // [512][128]
    const float* __restrict__ W2ih,   // [256][128]
    const float* __restrict__ W2hh,   // [256][64]
    const float* __restrict__ b2_ih,
    const float* __restrict__ b2_hh,
    const float* __restrict__ fc1w,
    const float* __restrict__ fc1b,
    const float* __restrict__ fc2w,
    const float* __restrict__ fc2b,
    float* __restrict__ out)
{
    extern __shared__ char smraw[];
    __half* Wihs = (__half*)smraw;
    __half* Whhs = (__half*)(smraw + SM_WIH);
    __half* xwb  = (__half*)(smraw + SM_WIH + SM_WHH);
    __half* hsh1 = (__half*)(smraw + SM_WIH + SM_WHH + SM_XWB);
    __half* hsh2 = (__half*)(smraw + SM_WIH + SM_WHH + SM_XWB + SM_HSH1);
    float*  hfin = (float*)(smraw + SM_WIH + SM_WHH + SM_XWB + SM_HSH1 + SM_HSH2);

    const int tid  = threadIdx.x;
    const int w    = tid >> 5;
    const int lane = tid & 31;
    const int bblk = blockIdx.x;
    const int b0   = bblk * 8;
    const int r    = lane >> 2;
    const int q    = lane & 3;
    const int n0   = q * 2;
    const bool lo  = (r < 4);
    const int ncol = n0 + (lo ? 0 : 1);

    // ---- L1 mapping ----
    int uu[2], Glo1[2], Ghi1[2];
#pragma unroll
    for (int mt = 0; mt < 2; mt++) {
        uu[mt]   = w * 8 + mt * 4 + (r & 3);
        Glo1[mt] = (r >> 2) * H1c + uu[mt];
        Ghi1[mt] = ((r + 8) >> 2) * H1c + uu[mt];
    }
    uint32_t afr[2][8][4];
#pragma unroll
    for (int mt = 0; mt < 2; mt++) {
        const float* rl = W1hh + (size_t)Glo1[mt] * H1c;
        const float* rh = W1hh + (size_t)Ghi1[mt] * H1c;
#pragma unroll
        for (int ks = 0; ks < 8; ks++) {
            int k = ks * 16 + q * 2;
            afr[mt][ks][0] = packh2(rl[k],     rl[k + 1]);
            afr[mt][ks][1] = packh2(rh[k],     rh[k + 1]);
            afr[mt][ks][2] = packh2(rl[k + 8], rl[k + 9]);
            afr[mt][ks][3] = packh2(rh[k + 8], rh[k + 9]);
        }
    }

    // ---- L2 mapping ----
    const int u    = w * 4 + (r & 3);
    const int Glo2 = (r >> 2) * H2c + u;
    const int Ghi2 = ((r + 8) >> 2) * H2c + u;
    const float blo = __ldg(b2_ih + Glo2) + __ldg(b2_hh + Glo2);
    const float bhi = __ldg(b2_ih + Ghi2) + __ldg(b2_hh + Ghi2);

    // ---- stage W2 into smem (permuted rows) ----
    for (int idx = tid; idx < 256 * 128; idx += 512) {
        int tr = idx >> 7, k = idx & 127;
        int pr = tr & 15, ww = tr >> 4;
        int src = (pr >> 2) * 64 + ww * 4 + (pr & 3);
        Wihs[tr * WISf + k] = __float2half_rn(W2ih[(size_t)src * 128 + k]);
    }
    for (int idx = tid; idx < 256 * 64; idx += 512) {
        int tr = idx >> 6, k = idx & 63;
        int pr = tr & 15, ww = tr >> 4;
        int src = (pr >> 2) * 64 + ww * 4 + (pr & 3);
        Whhs[tr * WHSf + k] = __float2half_rn(W2hh[(size_t)src * 64 + k]);
    }

    for (int i = tid; i < 2 * 8 * HP1f / 2; i += 512)
        ((__half2*)hsh1)[i] = __floats2half2_rn(0.f, 0.f);
    for (int i = tid; i < 2 * 8 * HP2f / 2; i += 512)
        ((__half2*)hsh2)[i] = __floats2half2_rn(0.f, 0.f);

    // prefetch xw tile t=0: contiguous 8KB (512 threads x 16B)
    const __half* xg = xwp + (size_t)bblk * Tc * XWT;
    cp16(s2u(&xwb[0 * XWT + tid * 8]), xg + tid * 8);
    cp_commit();
    cp_wait0();
    __syncthreads();

    const uint32_t aih_base = s2u(Wihs + (w * 16 + (lane & 15)) * WISf + (lane >> 4) * 8);
    const uint32_t ahh_base = s2u(Whhs + (w * 16 + (lane & 15)) * WHSf + (lane >> 4) * 8);

    float cst1[2] = {0.f, 0.f};
    float cst2 = 0.f;

    for (int t = 0; t <= Tc; t++) {
        if (t + 1 < Tc) {
            cp16(s2u(&xwb[((t + 1) & 1) * XWT + tid * 8]), xg + (size_t)(t + 1) * XWT + tid * 8);
            cp_commit();
        }

        const __half* xb  = xwb + (t & 1) * XWT;
        const __half* hb1 = hsh1 + (t & 1) * 8 * HP1f;
        const __half* hb2 = hsh2 + (t & 1) * 8 * HP2f;
        const int l = lane & 15;

        // B fragments of h1[t-1] — shared by L1-hh and L2-ih
        uint32_t bf1[8][2];
        {
            uint32_t baddr = s2u(hb1 + (l & 7) * HP1f + ((l >> 3) & 1) * 8);
#pragma unroll
            for (int ks = 0; ks < 8; ks++)
                ldm_x2(bf1[ks][0], bf1[ks][1], baddr + ks * 32);
        }

        // ---- L1: h1[t] ----
        if (t < Tc) {
            float acc1[2][4];
#pragma unroll
            for (int mt = 0; mt < 2; mt++) {
                float2 vlo = __half22float2(*(const __half2*)(xb + Glo1[mt] * 8 + n0));
                float2 vhi = __half22float2(*(const __half2*)(xb + Ghi1[mt] * 8 + n0));
                acc1[mt][0] = vlo.x; acc1[mt][1] = vlo.y;
                acc1[mt][2] = vhi.x; acc1[mt][3] = vhi.y;
            }
#pragma unroll
            for (int ks = 0; ks < 8; ks++) {
                mma16816(acc1[0], afr[0][ks], bf1[ks]);
                mma16816(acc1[1], afr[1][ks], bf1[ks]);
            }
#pragma unroll
            for (int mt = 0; mt < 2; mt++) {
                float s0 = lo ? acc1[mt][1] : acc1[mt][0];
                float s1 = lo ? acc1[mt][3] : acc1[mt][2];
                float r0 = __shfl_xor_sync(0xffffffffu, s0, 16);
                float r1 = __shfl_xor_sync(0xffffffffu, s1, 16);
                float zi = lo ? acc1[mt][0] : r0;
                float zf = lo ? r0          : acc1[mt][1];
                float zg = lo ? acc1[mt][2] : r1;
                float zo = lo ? r1          : acc1[mt][3];

                cst1[mt] = sigfast(zf) * cst1[mt] + sigfast(zi) * tanhfast(zg);
                float h = sigfast(zo) * tanhfast(cst1[mt]);
                hsh1[((t + 1) & 1) * 8 * HP1f + ncol * HP1f + uu[mt]] = __float2half_rn(h);
            }
        }

        // ---- L2: h2[t-1] ----
        if (t >= 1) {
            uint32_t bf2[4][2];
            {
                uint32_t baddr = s2u(hb2 + (l & 7) * HP2f + ((l >> 3) & 1) * 8);
#pragma unroll
                for (int ks = 0; ks < 4; ks++)
                    ldm_x2(bf2[ks][0], bf2[ks][1], baddr + ks * 32);
            }
            float accA[4] = {blo, blo, bhi, bhi};
            float accC[4] = {0.f, 0.f, 0.f, 0.f};
#pragma unroll
            for (int ks = 0; ks < 8; ks++) {
                uint32_t a2[4];
                ldm_x4(a2[0], a2[1], a2[2], a2[3], aih_base + ks * 32);
                mma16816(accA, a2, bf1[ks]);
            }
#pragma unroll
            for (int ks = 0; ks < 4; ks++) {
                uint32_t a2[4];
                ldm_x4(a2[0], a2[1], a2[2], a2[3], ahh_base + ks * 32);
                mma16816(accC, a2, bf2[ks]);
            }
            float acc[4];
#pragma unroll
            for (int i = 0; i < 4; i++) acc[i] = accA[i] + accC[i];

            float s0 = lo ? acc[1] : acc[0];
            float s1 = lo ? acc[3] : acc[2];
            float r0 = __shfl_xor_sync(0xffffffffu, s0, 16);
            float r1 = __shfl_xor_sync(0xffffffffu, s1, 16);
            float zi = lo ? acc[0] : r0;
            float zf = lo ? r0     : acc[1];
            float zg = lo ? acc[2] : r1;
            float zo = lo ? r1     : acc[3];

            cst2 = sigfast(zf) * cst2 + sigfast(zi) * tanhfast(zg);
            float h = sigfast(zo) * tanhfast(cst2);

            if (t == Tc) hfin[ncol * 64 + u] = h;
            else hsh2[((t + 1) & 1) * 8 * HP2f + ncol * HP2f + u] = __float2half_rn(h);
        }

        cp_wait0();
        __syncthreads();
    }

    // FC head
    if (w < 8) {
        float a = __ldg(fc1b + lane);
#pragma unroll
        for (int k = 0; k < 64; k++)
            a = fmaf(hfin[w * 64 + k], __ldg(fc1w + lane * 64 + k), a);
        a = fmaxf(a, 0.f);
        float v = a * __ldg(fc2w + lane);
#pragma unroll
        for (int off = 16; off; off >>= 1) v += __shfl_down_sync(0xffffffffu, v, off);
        if (lane == 0) out[b0 + w] = 1.f / (1.f + __expf(-(v + __ldg(fc2b))));
    }
}

// ---------------------------------------------------------------------------
extern "C" void kernel_launch(void* const* d_in, const int* in_sizes, int n_in,
                              void* d_out, int out_size)
{
    (void)in_sizes; (void)n_in; (void)out_size;
    const float* X     = (const float*)d_in[0];
    const float* W1_ih = (const float*)d_in[1];
    const float* W1_hh = (const float*)d_in[2];
    const float* b1_ih = (const float*)d_in[3];
    const float* b1_hh = (const float*)d_in[4];
    const float* W2_ih = (const float*)d_in[5];
    const float* W2_hh = (const float*)d_in[6];
    const float* b2_ih = (const float*)d_in[7];
    const float* b2_hh = (const float*)d_in[8];
    const float* fc1w  = (const float*)d_in[9];
    const float* fc1b  = (const float*)d_in[10];
    const float* fc2w  = (const float*)d_in[11];
    const float* fc2b  = (const float*)d_in[12];
    float* out = (float*)d_out;

    __half *xh, *w1h, *xw1;
    cudaGetSymbolAddress((void**)&xh,  g_xh);
    cudaGetSymbolAddress((void**)&w1h, g_w1h);
    cudaGetSymbolAddress((void**)&xw1, g_xw1);

    static int attr_done = 0;
    if (!attr_done) {
        cudaFuncSetAttribute(lstm12_kernel, cudaFuncAttributeMaxDynamicSharedMemorySize, SMEMF);
        attr_done = 1;
    }

    // 0) pad+convert X and W1_ih to fp16 [..][112]
    convert_pad<<<(Mtot * (KP / 2) + 255) / 256, 256>>>(X, xh, Mtot);
    convert_pad<<<(G1c * (KP / 2) + 255) / 256, 256>>>(W1_ih, w1h, G1c);
    // 1) xw1p = half(X @ W1_ih^T + b), PERMUTED [bblk][t][gate][8]
    gemm1hp<<<dim3(G1c / 128, Mtot / 128), 256>>>(xh, w1h, b1_ih, b1_hh, xw1);
    // 2) fused layer-1 + layer-2 recurrence + FC head
    lstm12_kernel<<<Bc / 8, 512, SMEMF>>>(xw1, W1_hh, W2_ih, W2_hh, b2_ih, b2_hh,
                                          fc1w, fc1b, fc2w, fc2b, out);
}